// round 15
// baseline (speedup 1.0000x reference)
#include <cuda_runtime.h>
#include <cuda_fp16.h>
#include <math_constants.h>
#include <cstdint>

#define BATCH   4
#define SEQ     2048
#define DIM     1024
#define HEADS   16
#define HDIM    64
#define MROWS   (BATCH * SEQ)          // 8192
#define SCALE   0.125f                 // 1/sqrt(64)
#define QSCALE  0.1803368801111244f    // SCALE * log2(e)

#define GSTR    72                     // gemm smem row stride (halfs, 144B)
#define QSTR    72                     // flash smem row stride (halfs, 144B)

// ---------------------------------------------------------------------------
// Scratch (fp16 resident)
// ---------------------------------------------------------------------------
__device__ __half g_Xh[MROWS * DIM];                 // [b*s][dim]
__device__ __half g_WTh[4 * DIM * DIM];              // W^T fp16
__device__ __half g_Qh[MROWS * DIM];                 // pre-scaled by SCALE*log2e
__device__ __half g_Kh[MROWS * DIM];
__device__ __half g_Vh[BATCH * HEADS * HDIM * SEQ];  // [b][h][d][s]
__device__ __half g_attnh[MROWS * DIM];

// ---------------------------------------------------------------------------
// Helpers
// ---------------------------------------------------------------------------
__device__ __forceinline__ uint32_t f2h2(float lo, float hi) {
    uint32_t r;
    asm("cvt.rn.f16x2.f32 %0, %1, %2;" : "=r"(r) : "f"(hi), "f"(lo));
    return r;
}
__device__ __forceinline__ float ex2(float x) {
    float y; asm("ex2.approx.f32 %0, %1;" : "=f"(y) : "f"(x)); return y;
}
__device__ __forceinline__ void st_h8(void* dst, float4 u, float4 v) {
    uint4 o;
    o.x = f2h2(u.x, u.y); o.y = f2h2(u.z, u.w);
    o.z = f2h2(v.x, v.y); o.w = f2h2(v.z, v.w);
    *(uint4*)dst = o;
}
__device__ __forceinline__ void ldsm4(uint32_t* r, uint32_t addr) {
    asm volatile("ldmatrix.sync.aligned.m8n8.x4.shared.b16 {%0,%1,%2,%3}, [%4];"
        : "=r"(r[0]), "=r"(r[1]), "=r"(r[2]), "=r"(r[3]) : "r"(addr));
}
__device__ __forceinline__ void mma_f16(float* d, const uint32_t* a,
                                        uint32_t b0, uint32_t b1) {
    asm volatile("mma.sync.aligned.m16n8k16.row.col.f32.f16.f16.f32 "
        "{%0,%1,%2,%3}, {%4,%5,%6,%7}, {%8,%9}, {%0,%1,%2,%3};"
        : "+f"(d[0]), "+f"(d[1]), "+f"(d[2]), "+f"(d[3])
        : "r"(a[0]), "r"(a[1]), "r"(a[2]), "r"(a[3]), "r"(b0), "r"(b1));
}
__device__ __forceinline__ uint32_t s2u(const void* p) {
    uint32_t a;
    asm("{ .reg .u64 t; cvta.to.shared.u64 t, %1; cvt.u32.u64 %0, t; }"
        : "=r"(a) : "l"(p));
    return a;
}
__device__ __forceinline__ void cp16(uint32_t dst, const void* src) {
    asm volatile("cp.async.cg.shared.global [%0], [%1], 16;"
                 :: "r"(dst), "l"(src));
}
#define CP_COMMIT() asm volatile("cp.async.commit_group;")
#define CP_WAIT(n)  asm volatile("cp.async.wait_group %0;" :: "n"(n))

// ---------------------------------------------------------------------------
// Elementwise convert X -> fp16
// ---------------------------------------------------------------------------
__global__ __launch_bounds__(256)
void conv_x(const float* __restrict__ X, __half* __restrict__ Xh)
{
    const size_t i = ((size_t)blockIdx.x * 256 + threadIdx.x) * 8;
    float4 a = *(const float4*)(X + i);
    float4 b = *(const float4*)(X + i + 4);
    st_h8(Xh + i, a, b);
}

// ---------------------------------------------------------------------------
// Weight transpose + convert
// ---------------------------------------------------------------------------
__global__ __launch_bounds__(256)
void transpose_w(const float* __restrict__ Wq, const float* __restrict__ Wk,
                 const float* __restrict__ Wv, const float* __restrict__ Wo,
                 __half* __restrict__ outb)
{
    __shared__ float t[32][33];
    const int z = blockIdx.z;
    const float* in = (z == 0) ? Wq : (z == 1) ? Wk : (z == 2) ? Wv : Wo;
    __half* out = outb + (size_t)z * DIM * DIM;
    const int x = blockIdx.x * 32 + threadIdx.x;
    #pragma unroll
    for (int j = 0; j < 4; j++) {
        int y = blockIdx.y * 32 + threadIdx.y + j * 8;
        t[threadIdx.y + j * 8][threadIdx.x] = in[(size_t)y * DIM + x];
    }
    __syncthreads();
    const int ox = blockIdx.y * 32 + threadIdx.x;
    #pragma unroll
    for (int j = 0; j < 4; j++) {
        int oy = blockIdx.x * 32 + threadIdx.y + j * 8;
        out[(size_t)oy * DIM + ox] = __float2half_rn(t[threadIdx.x][threadIdx.y + j * 8]);
    }
}

// ---------------------------------------------------------------------------
// fp16 GEMM: 128 threads, 4 warps of 64x64; BK=64, 3-stage cp.async ring,
// ONE sync per iteration. Block tile 128x128. (unchanged from round 14)
// ---------------------------------------------------------------------------
#define STAGE_H  (2 * 128 * GSTR)
#define STAGE_B  (STAGE_H * 2)
#define NKT      (DIM / 64)            // 16
#define GEMM_SMEM (3 * STAGE_B)

__device__ __forceinline__ void g_issue(const __half* Ab, const __half* Bb,
                                        int kt, uint32_t stage_base, int tid)
{
    #pragma unroll
    for (int l = 0; l < 8; l++) {
        const int idx = tid + l * 128;
        const int row = idx >> 3;            // 0..127
        const int c   = (idx & 7) * 8;       // half col 0..56
        cp16(stage_base + (row * GSTR + c) * 2,
             Ab + (size_t)row * DIM + kt * 64 + c);
        cp16(stage_base + (128 * GSTR + row * GSTR + c) * 2,
             Bb + (size_t)row * DIM + kt * 64 + c);
    }
    CP_COMMIT();
}

__device__ __forceinline__ void g_mainloop(const __half* Ab, const __half* Bb,
                                           __half* sm, float acc[4][8][4])
{
    const int tid = threadIdx.x, warp = tid >> 5, lane = tid & 31;
    const int lr = lane & 7, sel = lane >> 3;
    const int lr8 = lr + (sel & 1) * 8;
    const int wm = warp >> 1, wn = warp & 1;      // 2x2 warp grid, 64x64 each
    const int arow = wm * 64 + lr8;
    const int brow = wn * 64 + lr8;
    const int colb = (sel >> 1) * 8;
    const uint32_t base = s2u(sm);

    g_issue(Ab, Bb, 0, base, tid);
    g_issue(Ab, Bb, 1, base + STAGE_B, tid);

    int slot = 0;
    for (int kt = 0; kt < NKT; kt++) {
        if (kt == NKT - 1) { CP_WAIT(0); } else { CP_WAIT(1); }
        __syncthreads();
        if (kt + 2 < NKT) {
            int ns = slot + 2; if (ns >= 3) ns -= 3;
            g_issue(Ab, Bb, kt + 2, base + ns * STAGE_B, tid);
        }
        const uint32_t as = base + slot * STAGE_B;
        const uint32_t bs = as + 128 * GSTR * 2;
        #pragma unroll
        for (int ks = 0; ks < 4; ks++) {
            const int co = ks * 16 + colb;
            uint32_t af[4][4], bq[4][4];
            #pragma unroll
            for (int mt = 0; mt < 4; mt++)
                ldsm4(af[mt], as + ((arow + mt * 16) * GSTR + co) * 2);
            #pragma unroll
            for (int pr = 0; pr < 4; pr++)
                ldsm4(bq[pr], bs + ((brow + pr * 16) * GSTR + co) * 2);
            #pragma unroll
            for (int mt = 0; mt < 4; mt++)
                #pragma unroll
                for (int nt = 0; nt < 8; nt++)
                    mma_f16(acc[mt][nt], af[mt],
                            bq[nt >> 1][nt & 1], bq[nt >> 1][(nt & 1) + 2]);
        }
        if (++slot == 3) slot = 0;
    }
}

// Epilogues (4-warp 64x64 mapping)
__device__ __forceinline__ void g_epi_h(float acc[4][8][4], const float* bias,
                                        __half* C, int bx, int by, float sc)
{
    const int warp = threadIdx.x >> 5, lane = threadIdx.x & 31;
    const int wm = warp >> 1, wn = warp & 1;
    const int mbase = by * 128 + wm * 64 + (lane >> 2);
    const int nbase = bx * 128 + wn * 64 + (lane & 3) * 2;
    #pragma unroll
    for (int mt = 0; mt < 4; mt++) {
        #pragma unroll
        for (int nt = 0; nt < 8; nt++) {
            const int c = nbase + nt * 8;
            const float b0 = __ldg(bias + c), b1 = __ldg(bias + c + 1);
            const int r0 = mbase + mt * 16, r1 = r0 + 8;
            *(__half2*)(C + (size_t)r0 * DIM + c) =
                __floats2half2_rn((acc[mt][nt][0] + b0) * sc, (acc[mt][nt][1] + b1) * sc);
            *(__half2*)(C + (size_t)r1 * DIM + c) =
                __floats2half2_rn((acc[mt][nt][2] + b0) * sc, (acc[mt][nt][3] + b1) * sc);
        }
    }
}
__device__ __forceinline__ void g_epi_trans_h(float acc[4][8][4], const float* bias,
                                              __half* C, int bx, int by)
{
    const int warp = threadIdx.x >> 5, lane = threadIdx.x & 31;
    const int wm = warp >> 1, wn = warp & 1;
    const int mbase = by * 128 + wm * 64 + (lane >> 2);
    const int nbase = bx * 128 + wn * 64 + (lane & 3) * 2;
    #pragma unroll
    for (int mt = 0; mt < 4; mt++) {
        #pragma unroll
        for (int nt = 0; nt < 8; nt++) {
            const int c = nbase + nt * 8;
            const float b0 = __ldg(bias + c), b1 = __ldg(bias + c + 1);
            const int r0 = mbase + mt * 16, r1 = r0 + 8;
            const int b_ = r0 >> 11, s0 = r0 & 2047, s1 = s0 + 8;
            const int h = c >> 6, hc = c & 63;
            const size_t base = (size_t)(b_ * HEADS + h) * HDIM;
            C[(base + hc) * SEQ + s0]     = __float2half_rn(acc[mt][nt][0] + b0);
            C[(base + hc + 1) * SEQ + s0] = __float2half_rn(acc[mt][nt][1] + b1);
            C[(base + hc) * SEQ + s1]     = __float2half_rn(acc[mt][nt][2] + b0);
            C[(base + hc + 1) * SEQ + s1] = __float2half_rn(acc[mt][nt][3] + b1);
        }
    }
}
__device__ __forceinline__ void g_epi_f32(float acc[4][8][4], const float* bias,
                                          float* C, int bx, int by)
{
    const int warp = threadIdx.x >> 5, lane = threadIdx.x & 31;
    const int wm = warp >> 1, wn = warp & 1;
    const int mbase = by * 128 + wm * 64 + (lane >> 2);
    const int nbase = bx * 128 + wn * 64 + (lane & 3) * 2;
    #pragma unroll
    for (int mt = 0; mt < 4; mt++) {
        #pragma unroll
        for (int nt = 0; nt < 8; nt++) {
            const int c = nbase + nt * 8;
            const float b0 = __ldg(bias + c), b1 = __ldg(bias + c + 1);
            const int r0 = mbase + mt * 16, r1 = r0 + 8;
            *(float2*)(C + (size_t)r0 * DIM + c) =
                make_float2(acc[mt][nt][0] + b0, acc[mt][nt][1] + b1);
            *(float2*)(C + (size_t)r1 * DIM + c) =
                make_float2(acc[mt][nt][2] + b0, acc[mt][nt][3] + b1);
        }
    }
}

// QKV fused projection: z = 0 (Q, pre-scaled by SCALE*log2e), 1 (K), 2 (V trans)
__global__ __launch_bounds__(128)
void qkv_h(const __half* __restrict__ X, const __half* __restrict__ WT,
           const float* __restrict__ bq, const float* __restrict__ bk,
           const float* __restrict__ bv,
           __half* __restrict__ q, __half* __restrict__ k, __half* __restrict__ v)
{
    extern __shared__ __half smh[];
    const int z = blockIdx.z;
    const __half* Ab = X + (size_t)blockIdx.y * 128 * DIM;
    const __half* Bb = WT + (size_t)z * DIM * DIM + (size_t)blockIdx.x * 128 * DIM;

    float acc[4][8][4];
    #pragma unroll
    for (int i = 0; i < 4; i++)
        #pragma unroll
        for (int j = 0; j < 8; j++)
            #pragma unroll
            for (int r = 0; r < 4; r++) acc[i][j][r] = 0.f;

    g_mainloop(Ab, Bb, smh, acc);

    if (z == 2)      g_epi_trans_h(acc, bv, v, blockIdx.x, blockIdx.y);
    else if (z == 1) g_epi_h(acc, bk, k, blockIdx.x, blockIdx.y, 1.f);
    else             g_epi_h(acc, bq, q, blockIdx.x, blockIdx.y, QSCALE);
}

// Output projection (f32 out)
__global__ __launch_bounds__(128)
void out_h(const __half* __restrict__ A, const __half* __restrict__ BT,
           const float* __restrict__ bias, float* __restrict__ C)
{
    extern __shared__ __half smh[];
    const __half* Ab = A + (size_t)blockIdx.y * 128 * DIM;
    const __half* Bb = BT + (size_t)blockIdx.x * 128 * DIM;

    float acc[4][8][4];
    #pragma unroll
    for (int i = 0; i < 4; i++)
        #pragma unroll
        for (int j = 0; j < 8; j++)
            #pragma unroll
            for (int r = 0; r < 4; r++) acc[i][j][r] = 0.f;

    g_mainloop(Ab, Bb, smh, acc);
    g_epi_f32(acc, bias, C, blockIdx.x, blockIdx.y);
}

// ---------------------------------------------------------------------------
// Fused flash attention (256 threads, 16 q rows/warp, 3 CTAs/SM,
// max-free ex2 softmax, register P, mma row sums). t-loop body factored and
// unrolled 2x so per-parity ldsm addresses become loop-invariant.
// ---------------------------------------------------------------------------
#define KVSTAGE_H (2 * 64 * QSTR)
#define KVSTAGE_B (KVSTAGE_H * 2)
#define FLASH_SMEM ((128 * QSTR + 2 * KVSTAGE_H) * 2)

__device__ __forceinline__ void f_issue_kv(const __half* Kb, const __half* Vb,
                                           int kv, uint32_t kvb, int tid)
{
    #pragma unroll
    for (int l = 0; l < 2; l++) {
        const int idx = tid + l * 256;
        const int row = idx >> 3;
        const int c   = (idx & 7) * 8;
        cp16(kvb + (row * QSTR + c) * 2, Kb + (size_t)(kv + row) * DIM + c);
        cp16(kvb + ((64 + row) * QSTR + c) * 2, Vb + (size_t)row * SEQ + kv + c);
    }
    CP_COMMIT();
}

struct FlashState {
    float acc_o[8][4];
    float acc_s[4];
    uint32_t qf[4][4];
    uint32_t bones;
    int lr8, colb, tid;
};

__device__ __forceinline__ void f_iter(FlashState& st, int t, int NT,
                                       const __half* Kb, const __half* Vb,
                                       uint32_t kv_base, uint32_t ksb)
{
    CP_WAIT(0);
    __syncthreads();
    if (t + 1 < NT)
        f_issue_kv(Kb, Vb, (t + 1) * 64,
                   kv_base + ((t + 1) & 1) * KVSTAGE_B, st.tid);

    const uint32_t vsb = ksb + 64 * QSTR * 2;

    // ---- S' = (Q*scale*log2e) K^T ----
    float s[8][4];
    #pragma unroll
    for (int nt = 0; nt < 8; nt++)
        #pragma unroll
        for (int r = 0; r < 4; r++) s[nt][r] = 0.f;
    #pragma unroll
    for (int ks = 0; ks < 4; ks++) {
        const int co = ks * 16 + st.colb;
        uint32_t kf[4][4];
        #pragma unroll
        for (int p = 0; p < 4; p++)
            ldsm4(kf[p], ksb + ((p * 16 + st.lr8) * QSTR + co) * 2);
        #pragma unroll
        for (int nt = 0; nt < 8; nt++)
            mma_f16(s[nt], st.qf[ks],
                    kf[nt >> 1][nt & 1], kf[nt >> 1][(nt & 1) + 2]);
    }

    // ---- P = exp2(S') (no max pass) ----
    #pragma unroll
    for (int nt = 0; nt < 8; nt++) {
        s[nt][0] = ex2(s[nt][0]);
        s[nt][1] = ex2(s[nt][1]);
        s[nt][2] = ex2(s[nt][2]);
        s[nt][3] = ex2(s[nt][3]);
    }

    // ---- O += P V; row sums via ones-column mma ----
    #pragma unroll
    for (int ks = 0; ks < 4; ks++) {
        uint32_t af[4];
        af[0] = f2h2(s[2 * ks][0],     s[2 * ks][1]);
        af[1] = f2h2(s[2 * ks][2],     s[2 * ks][3]);
        af[2] = f2h2(s[2 * ks + 1][0], s[2 * ks + 1][1]);
        af[3] = f2h2(s[2 * ks + 1][2], s[2 * ks + 1][3]);
        const int co = ks * 16 + st.colb;
        uint32_t vf[4][4];
        #pragma unroll
        for (int p = 0; p < 4; p++)
            ldsm4(vf[p], vsb + ((p * 16 + st.lr8) * QSTR + co) * 2);
        #pragma unroll
        for (int nt = 0; nt < 8; nt++)
            mma_f16(st.acc_o[nt], af,
                    vf[nt >> 1][nt & 1], vf[nt >> 1][(nt & 1) + 2]);
        mma_f16(st.acc_s, af, st.bones, st.bones);
    }
}

__global__ __launch_bounds__(256, 3)
void flash_h(const __half* __restrict__ Q, const __half* __restrict__ K,
             const __half* __restrict__ Vt, __half* __restrict__ Out)
{
    extern __shared__ __half smh[];
    __half* Ps = smh;                       // Q staging only
    const uint32_t ps_base = s2u(Ps);
    const uint32_t kv_base = s2u(smh + 128 * QSTR);

    const int tid = threadIdx.x, warp = tid >> 5, lane = tid & 31;
    const int lr = lane & 7, sel = lane >> 3;
    const int h = blockIdx.y, b = blockIdx.z;
    const int q0 = blockIdx.x * 128;

    const __half* Qb = Q + ((size_t)b * SEQ + q0) * DIM + h * HDIM;
    const __half* Kb = K + (size_t)b * SEQ * DIM + h * HDIM;
    const __half* Vb = Vt + (size_t)(b * HEADS + h) * HDIM * SEQ;

    // ---- Q tile via cp.async (group 0), KV tile 0 (group 1) ----
    #pragma unroll
    for (int l = 0; l < 4; l++) {
        const int idx = tid + l * 256;
        const int row = idx >> 3, c = (idx & 7) * 8;
        cp16(ps_base + (row * QSTR + c) * 2, Qb + (size_t)row * DIM + c);
    }
    CP_COMMIT();
    f_issue_kv(Kb, Vb, 0, kv_base, tid);

    CP_WAIT(1);
    __syncthreads();

    FlashState st;
    st.tid = tid;
    st.lr8 = lr + (sel & 1) * 8;
    st.colb = (sel >> 1) * 8;
    st.bones = (lane < 4) ? 0x3C003C00u : 0u;

    const int arow = warp * 16 + st.lr8;
    #pragma unroll
    for (int ks = 0; ks < 4; ks++)
        ldsm4(st.qf[ks], ps_base + (arow * QSTR + ks * 16 + st.colb) * 2);

    #pragma unroll
    for (int i = 0; i < 8; i++)
        #pragma unroll
        for (int r = 0; r < 4; r++) st.acc_o[i][r] = 0.f;
    #pragma unroll
    for (int r = 0; r < 4; r++) st.acc_s[r] = 0.f;

    const int NT = SEQ / 64;    // 32, even
    for (int t = 0; t < NT; t += 2) {
        f_iter(st, t,     NT, Kb, Vb, kv_base, kv_base);
        f_iter(st, t + 1, NT, Kb, Vb, kv_base, kv_base + KVSTAGE_B);
    }

    // ---- epilogue ----
    const int src = lane & ~3;
    const float l0 = __shfl_sync(0xffffffff, st.acc_s[0], src);
    const float l1 = __shfl_sync(0xffffffff, st.acc_s[2], src);
    const float inv0 = 1.f / l0, inv1 = 1.f / l1;
    const int r0 = q0 + warp * 16 + (lane >> 2);
    const int r1 = r0 + 8;
    __half* Ob0 = Out + ((size_t)b * SEQ + r0) * DIM + h * HDIM;
    __half* Ob1 = Out + ((size_t)b * SEQ + r1) * DIM + h * HDIM;
    #pragma unroll
    for (int nt = 0; nt < 8; nt++) {
        const int c = nt * 8 + (lane & 3) * 2;
        *(__half2*)(Ob0 + c) =
            __floats2half2_rn(st.acc_o[nt][0] * inv0, st.acc_o[nt][1] * inv0);
        *(__half2*)(Ob1 + c) =
            __floats2half2_rn(st.acc_o[nt][2] * inv1, st.acc_o[nt][3] * inv1);
    }
}

// ---------------------------------------------------------------------------
// kernel_launch
// ---------------------------------------------------------------------------
extern "C" void kernel_launch(void* const* d_in, const int* in_sizes, int n_in,
                              void* d_out, int out_size)
{
    const float* X  = (const float*)d_in[0];
    const float* Wq = (const float*)d_in[1];
    const float* bq = (const float*)d_in[2];
    const float* Wk = (const float*)d_in[3];
    const float* bk = (const float*)d_in[4];
    const float* Wv = (const float*)d_in[5];
    const float* bv = (const float*)d_in[6];
    const float* Wo = (const float*)d_in[7];
    const float* bo = (const float*)d_in[8];
    float* out = (float*)d_out;

    __half *xh, *wt, *qh, *kh, *vh, *ah;
    cudaGetSymbolAddress((void**)&xh, g_Xh);
    cudaGetSymbolAddress((void**)&wt, g_WTh);
    cudaGetSymbolAddress((void**)&qh, g_Qh);
    cudaGetSymbolAddress((void**)&kh, g_Kh);
    cudaGetSymbolAddress((void**)&vh, g_Vh);
    cudaGetSymbolAddress((void**)&ah, g_attnh);

    static bool attr_set = false;
    if (!attr_set) {
        cudaFuncSetAttribute(qkv_h,
            cudaFuncAttributeMaxDynamicSharedMemorySize, GEMM_SMEM);
        cudaFuncSetAttribute(out_h,
            cudaFuncAttributeMaxDynamicSharedMemorySize, GEMM_SMEM);
        cudaFuncSetAttribute(flash_h,
            cudaFuncAttributeMaxDynamicSharedMemorySize, FLASH_SMEM);
        attr_set = true;
    }

    // 1. Convert X, transpose+convert W
    conv_x<<<MROWS * DIM / (256 * 8), 256>>>(X, xh);
    const dim3 tGrid(DIM / 32, DIM / 32, 4);
    const dim3 tBlk(32, 8);
    transpose_w<<<tGrid, tBlk>>>(Wq, Wk, Wv, Wo, wt);

    // 2. QKV projections (128 threads, 4 warps of 64x64)
    const dim3 qkvGrid(DIM / 128, MROWS / 128, 3);   // (8, 64, 3)
    qkv_h<<<qkvGrid, 128, GEMM_SMEM>>>(xh, wt, bq, bk, bv, qh, kh, vh);

    // 3. Fused attention
    const dim3 faGrid(SEQ / 128, HEADS, BATCH);      // (16, 16, 4)
    flash_h<<<faGrid, 256, FLASH_SMEM>>>(qh, kh, vh, ah);

    // 4. Output projection
    const dim3 projGrid(DIM / 128, MROWS / 128);     // (8, 64)
    out_h<<<projGrid, 128, GEMM_SMEM>>>(ah, wt + 3 * (size_t)DIM * DIM, bo, out);
}

// round 16
// speedup vs baseline: 1.0139x; 1.0139x over previous
#include <cuda_runtime.h>
#include <cuda_fp16.h>
#include <math_constants.h>
#include <cstdint>

#define BATCH   4
#define SEQ     2048
#define DIM     1024
#define HEADS   16
#define HDIM    64
#define MROWS   (BATCH * SEQ)          // 8192
#define SCALE   0.125f                 // 1/sqrt(64)
#define QSCALE  0.1803368801111244f    // SCALE * log2(e)

#define GSTR    72                     // gemm smem row stride (halfs, 144B)
#define QSTR    72                     // flash smem row stride (halfs, 144B)

// ---------------------------------------------------------------------------
// Scratch (fp16 resident)
// ---------------------------------------------------------------------------
__device__ __half g_Xh[MROWS * DIM];                 // [b*s][dim]
__device__ __half g_WTh[4 * DIM * DIM];              // W^T fp16
__device__ __half g_Qh[MROWS * DIM];                 // pre-scaled by SCALE*log2e
__device__ __half g_Kh[MROWS * DIM];
__device__ __half g_Vh[BATCH * HEADS * HDIM * SEQ];  // [b][h][d][s]
__device__ __half g_attnh[MROWS * DIM];

// ---------------------------------------------------------------------------
// Helpers
// ---------------------------------------------------------------------------
__device__ __forceinline__ uint32_t f2h2(float lo, float hi) {
    uint32_t r;
    asm("cvt.rn.f16x2.f32 %0, %1, %2;" : "=r"(r) : "f"(hi), "f"(lo));
    return r;
}
__device__ __forceinline__ float ex2(float x) {
    float y; asm("ex2.approx.f32 %0, %1;" : "=f"(y) : "f"(x)); return y;
}
__device__ __forceinline__ void st_h8(void* dst, float4 u, float4 v) {
    uint4 o;
    o.x = f2h2(u.x, u.y); o.y = f2h2(u.z, u.w);
    o.z = f2h2(v.x, v.y); o.w = f2h2(v.z, v.w);
    *(uint4*)dst = o;
}
__device__ __forceinline__ void ldsm4(uint32_t* r, uint32_t addr) {
    asm volatile("ldmatrix.sync.aligned.m8n8.x4.shared.b16 {%0,%1,%2,%3}, [%4];"
        : "=r"(r[0]), "=r"(r[1]), "=r"(r[2]), "=r"(r[3]) : "r"(addr));
}
__device__ __forceinline__ void mma_f16(float* d, const uint32_t* a,
                                        uint32_t b0, uint32_t b1) {
    asm volatile("mma.sync.aligned.m16n8k16.row.col.f32.f16.f16.f32 "
        "{%0,%1,%2,%3}, {%4,%5,%6,%7}, {%8,%9}, {%0,%1,%2,%3};"
        : "+f"(d[0]), "+f"(d[1]), "+f"(d[2]), "+f"(d[3])
        : "r"(a[0]), "r"(a[1]), "r"(a[2]), "r"(a[3]), "r"(b0), "r"(b1));
}
__device__ __forceinline__ uint32_t s2u(const void* p) {
    uint32_t a;
    asm("{ .reg .u64 t; cvta.to.shared.u64 t, %1; cvt.u32.u64 %0, t; }"
        : "=r"(a) : "l"(p));
    return a;
}
__device__ __forceinline__ void cp16(uint32_t dst, const void* src) {
    asm volatile("cp.async.cg.shared.global [%0], [%1], 16;"
                 :: "r"(dst), "l"(src));
}
#define CP_COMMIT() asm volatile("cp.async.commit_group;")
#define CP_WAIT(n)  asm volatile("cp.async.wait_group %0;" :: "n"(n))

// ---------------------------------------------------------------------------
// Prep: z = 0..3 -> transpose+convert W_z;  z = 4 -> convert X (32 f/thread)
// Block (32, 8) = 256 threads; grid (32, 32, 5).
// ---------------------------------------------------------------------------
__global__ __launch_bounds__(256)
void prep(const float* __restrict__ X,
          const float* __restrict__ Wq, const float* __restrict__ Wk,
          const float* __restrict__ Wv, const float* __restrict__ Wo,
          __half* __restrict__ Xh, __half* __restrict__ outb)
{
    const int z = blockIdx.z;
    if (z == 4) {
        const int lb  = blockIdx.y * 32 + blockIdx.x;          // 0..1023
        const int tid = threadIdx.y * 32 + threadIdx.x;        // 0..255
        const size_t base = (size_t)lb * (256 * 32);
        #pragma unroll
        for (int j = 0; j < 4; j++) {
            const size_t i = base + (size_t)(j * 256 + tid) * 8;
            float4 a = *(const float4*)(X + i);
            float4 b = *(const float4*)(X + i + 4);
            st_h8(Xh + i, a, b);
        }
        return;
    }
    __shared__ float t[32][33];
    const float* in = (z == 0) ? Wq : (z == 1) ? Wk : (z == 2) ? Wv : Wo;
    __half* out = outb + (size_t)z * DIM * DIM;
    const int x = blockIdx.x * 32 + threadIdx.x;
    #pragma unroll
    for (int j = 0; j < 4; j++) {
        int y = blockIdx.y * 32 + threadIdx.y + j * 8;
        t[threadIdx.y + j * 8][threadIdx.x] = in[(size_t)y * DIM + x];
    }
    __syncthreads();
    const int ox = blockIdx.y * 32 + threadIdx.x;
    #pragma unroll
    for (int j = 0; j < 4; j++) {
        int oy = blockIdx.x * 32 + threadIdx.y + j * 8;
        out[(size_t)oy * DIM + ox] = __float2half_rn(t[threadIdx.x][threadIdx.y + j * 8]);
    }
}

// ---------------------------------------------------------------------------
// fp16 GEMM: 128 threads, 4 warps of 64x64; BK=64, 3-stage cp.async ring,
// ONE sync per iteration. Block tile 128x128. (round-14 proven form)
// ---------------------------------------------------------------------------
#define STAGE_H  (2 * 128 * GSTR)
#define STAGE_B  (STAGE_H * 2)
#define NKT      (DIM / 64)            // 16
#define GEMM_SMEM (3 * STAGE_B)

__device__ __forceinline__ void g_issue(const __half* Ab, const __half* Bb,
                                        int kt, uint32_t stage_base, int tid)
{
    #pragma unroll
    for (int l = 0; l < 8; l++) {
        const int idx = tid + l * 128;
        const int row = idx >> 3;            // 0..127
        const int c   = (idx & 7) * 8;       // half col 0..56
        cp16(stage_base + (row * GSTR + c) * 2,
             Ab + (size_t)row * DIM + kt * 64 + c);
        cp16(stage_base + (128 * GSTR + row * GSTR + c) * 2,
             Bb + (size_t)row * DIM + kt * 64 + c);
    }
    CP_COMMIT();
}

__device__ __forceinline__ void g_mainloop(const __half* Ab, const __half* Bb,
                                           __half* sm, float acc[4][8][4])
{
    const int tid = threadIdx.x, warp = tid >> 5, lane = tid & 31;
    const int lr = lane & 7, sel = lane >> 3;
    const int lr8 = lr + (sel & 1) * 8;
    const int wm = warp >> 1, wn = warp & 1;      // 2x2 warp grid, 64x64 each
    const int arow = wm * 64 + lr8;
    const int brow = wn * 64 + lr8;
    const int colb = (sel >> 1) * 8;
    const uint32_t base = s2u(sm);

    g_issue(Ab, Bb, 0, base, tid);
    g_issue(Ab, Bb, 1, base + STAGE_B, tid);

    int slot = 0;
    for (int kt = 0; kt < NKT; kt++) {
        if (kt == NKT - 1) { CP_WAIT(0); } else { CP_WAIT(1); }
        __syncthreads();
        if (kt + 2 < NKT) {
            int ns = slot + 2; if (ns >= 3) ns -= 3;
            g_issue(Ab, Bb, kt + 2, base + ns * STAGE_B, tid);
        }
        const uint32_t as = base + slot * STAGE_B;
        const uint32_t bs = as + 128 * GSTR * 2;
        #pragma unroll
        for (int ks = 0; ks < 4; ks++) {
            const int co = ks * 16 + colb;
            uint32_t af[4][4], bq[4][4];
            #pragma unroll
            for (int mt = 0; mt < 4; mt++)
                ldsm4(af[mt], as + ((arow + mt * 16) * GSTR + co) * 2);
            #pragma unroll
            for (int pr = 0; pr < 4; pr++)
                ldsm4(bq[pr], bs + ((brow + pr * 16) * GSTR + co) * 2);
            #pragma unroll
            for (int mt = 0; mt < 4; mt++)
                #pragma unroll
                for (int nt = 0; nt < 8; nt++)
                    mma_f16(acc[mt][nt], af[mt],
                            bq[nt >> 1][nt & 1], bq[nt >> 1][(nt & 1) + 2]);
        }
        if (++slot == 3) slot = 0;
    }
}

// Epilogues (4-warp 64x64 mapping)
__device__ __forceinline__ void g_epi_h(float acc[4][8][4], const float* bias,
                                        __half* C, int bx, int by, float sc)
{
    const int warp = threadIdx.x >> 5, lane = threadIdx.x & 31;
    const int wm = warp >> 1, wn = warp & 1;
    const int mbase = by * 128 + wm * 64 + (lane >> 2);
    const int nbase = bx * 128 + wn * 64 + (lane & 3) * 2;
    #pragma unroll
    for (int mt = 0; mt < 4; mt++) {
        #pragma unroll
        for (int nt = 0; nt < 8; nt++) {
            const int c = nbase + nt * 8;
            const float b0 = __ldg(bias + c), b1 = __ldg(bias + c + 1);
            const int r0 = mbase + mt * 16, r1 = r0 + 8;
            *(__half2*)(C + (size_t)r0 * DIM + c) =
                __floats2half2_rn((acc[mt][nt][0] + b0) * sc, (acc[mt][nt][1] + b1) * sc);
            *(__half2*)(C + (size_t)r1 * DIM + c) =
                __floats2half2_rn((acc[mt][nt][2] + b0) * sc, (acc[mt][nt][3] + b1) * sc);
        }
    }
}
__device__ __forceinline__ void g_epi_trans_h(float acc[4][8][4], const float* bias,
                                              __half* C, int bx, int by)
{
    const int warp = threadIdx.x >> 5, lane = threadIdx.x & 31;
    const int wm = warp >> 1, wn = warp & 1;
    const int mbase = by * 128 + wm * 64 + (lane >> 2);
    const int nbase = bx * 128 + wn * 64 + (lane & 3) * 2;
    #pragma unroll
    for (int mt = 0; mt < 4; mt++) {
        #pragma unroll
        for (int nt = 0; nt < 8; nt++) {
            const int c = nbase + nt * 8;
            const float b0 = __ldg(bias + c), b1 = __ldg(bias + c + 1);
            const int r0 = mbase + mt * 16, r1 = r0 + 8;
            const int b_ = r0 >> 11, s0 = r0 & 2047, s1 = s0 + 8;
            const int h = c >> 6, hc = c & 63;
            const size_t base = (size_t)(b_ * HEADS + h) * HDIM;
            C[(base + hc) * SEQ + s0]     = __float2half_rn(acc[mt][nt][0] + b0);
            C[(base + hc + 1) * SEQ + s0] = __float2half_rn(acc[mt][nt][1] + b1);
            C[(base + hc) * SEQ + s1]     = __float2half_rn(acc[mt][nt][2] + b0);
            C[(base + hc + 1) * SEQ + s1] = __float2half_rn(acc[mt][nt][3] + b1);
        }
    }
}
__device__ __forceinline__ void g_epi_f32(float acc[4][8][4], const float* bias,
                                          float* C, int bx, int by)
{
    const int warp = threadIdx.x >> 5, lane = threadIdx.x & 31;
    const int wm = warp >> 1, wn = warp & 1;
    const int mbase = by * 128 + wm * 64 + (lane >> 2);
    const int nbase = bx * 128 + wn * 64 + (lane & 3) * 2;
    #pragma unroll
    for (int mt = 0; mt < 4; mt++) {
        #pragma unroll
        for (int nt = 0; nt < 8; nt++) {
            const int c = nbase + nt * 8;
            const float b0 = __ldg(bias + c), b1 = __ldg(bias + c + 1);
            const int r0 = mbase + mt * 16, r1 = r0 + 8;
            *(float2*)(C + (size_t)r0 * DIM + c) =
                make_float2(acc[mt][nt][0] + b0, acc[mt][nt][1] + b1);
            *(float2*)(C + (size_t)r1 * DIM + c) =
                make_float2(acc[mt][nt][2] + b0, acc[mt][nt][3] + b1);
        }
    }
}

// QKV fused projection: z = 0 (Q, pre-scaled by SCALE*log2e), 1 (K), 2 (V trans)
__global__ __launch_bounds__(128)
void qkv_h(const __half* __restrict__ X, const __half* __restrict__ WT,
           const float* __restrict__ bq, const float* __restrict__ bk,
           const float* __restrict__ bv,
           __half* __restrict__ q, __half* __restrict__ k, __half* __restrict__ v)
{
    extern __shared__ __half smh[];
    const int z = blockIdx.z;
    const __half* Ab = X + (size_t)blockIdx.y * 128 * DIM;
    const __half* Bb = WT + (size_t)z * DIM * DIM + (size_t)blockIdx.x * 128 * DIM;

    float acc[4][8][4];
    #pragma unroll
    for (int i = 0; i < 4; i++)
        #pragma unroll
        for (int j = 0; j < 8; j++)
            #pragma unroll
            for (int r = 0; r < 4; r++) acc[i][j][r] = 0.f;

    g_mainloop(Ab, Bb, smh, acc);

    if (z == 2)      g_epi_trans_h(acc, bv, v, blockIdx.x, blockIdx.y);
    else if (z == 1) g_epi_h(acc, bk, k, blockIdx.x, blockIdx.y, 1.f);
    else             g_epi_h(acc, bq, q, blockIdx.x, blockIdx.y, QSCALE);
}

// Output projection (f32 out)
__global__ __launch_bounds__(128)
void out_h(const __half* __restrict__ A, const __half* __restrict__ BT,
           const float* __restrict__ bias, float* __restrict__ C)
{
    extern __shared__ __half smh[];
    const __half* Ab = A + (size_t)blockIdx.y * 128 * DIM;
    const __half* Bb = BT + (size_t)blockIdx.x * 128 * DIM;

    float acc[4][8][4];
    #pragma unroll
    for (int i = 0; i < 4; i++)
        #pragma unroll
        for (int j = 0; j < 8; j++)
            #pragma unroll
            for (int r = 0; r < 4; r++) acc[i][j][r] = 0.f;

    g_mainloop(Ab, Bb, smh, acc);
    g_epi_f32(acc, bias, C, blockIdx.x, blockIdx.y);
}

// ---------------------------------------------------------------------------
// Fused flash attention (round-14 proven form: 256 threads, 16 q rows/warp,
// 3 CTAs/SM, max-free ex2 softmax, register P, mma row sums).
// ---------------------------------------------------------------------------
#define KVSTAGE_H (2 * 64 * QSTR)
#define KVSTAGE_B (KVSTAGE_H * 2)
#define FLASH_SMEM ((128 * QSTR + 2 * KVSTAGE_H) * 2)

__device__ __forceinline__ void f_issue_kv(const __half* Kb, const __half* Vb,
                                           int kv, uint32_t kvb, int tid)
{
    #pragma unroll
    for (int l = 0; l < 2; l++) {
        const int idx = tid + l * 256;
        const int row = idx >> 3;
        const int c   = (idx & 7) * 8;
        cp16(kvb + (row * QSTR + c) * 2, Kb + (size_t)(kv + row) * DIM + c);
        cp16(kvb + ((64 + row) * QSTR + c) * 2, Vb + (size_t)row * SEQ + kv + c);
    }
    CP_COMMIT();
}

__global__ __launch_bounds__(256, 3)
void flash_h(const __half* __restrict__ Q, const __half* __restrict__ K,
             const __half* __restrict__ Vt, __half* __restrict__ Out)
{
    extern __shared__ __half smh[];
    __half* Ps = smh;                       // Q staging only
    const uint32_t ps_base = s2u(Ps);
    const uint32_t kv_base = s2u(smh + 128 * QSTR);

    const int tid = threadIdx.x, warp = tid >> 5, lane = tid & 31;
    const int lr = lane & 7, sel = lane >> 3;
    const int lr8 = lr + (sel & 1) * 8;
    const int h = blockIdx.y, b = blockIdx.z;
    const int q0 = blockIdx.x * 128;

    const __half* Qb = Q + ((size_t)b * SEQ + q0) * DIM + h * HDIM;
    const __half* Kb = K + (size_t)b * SEQ * DIM + h * HDIM;
    const __half* Vb = Vt + (size_t)(b * HEADS + h) * HDIM * SEQ;

    // ---- Q tile via cp.async (group 0), KV tile 0 (group 1) ----
    #pragma unroll
    for (int l = 0; l < 4; l++) {
        const int idx = tid + l * 256;
        const int row = idx >> 3, c = (idx & 7) * 8;
        cp16(ps_base + (row * QSTR + c) * 2, Qb + (size_t)row * DIM + c);
    }
    CP_COMMIT();
    f_issue_kv(Kb, Vb, 0, kv_base, tid);

    CP_WAIT(1);
    __syncthreads();

    const int arow = warp * 16 + lr8;
    const int colb = (sel >> 1) * 8;
    uint32_t qf[4][4];
    #pragma unroll
    for (int ks = 0; ks < 4; ks++)
        ldsm4(qf[ks], ps_base + (arow * QSTR + ks * 16 + colb) * 2);

    // ones-column B fragment for row sums
    const uint32_t bones = (lane < 4) ? 0x3C003C00u : 0u;

    float acc_o[8][4];
    #pragma unroll
    for (int i = 0; i < 8; i++)
        #pragma unroll
        for (int r = 0; r < 4; r++) acc_o[i][r] = 0.f;
    float acc_s[4] = {0.f, 0.f, 0.f, 0.f};

    const int NT = SEQ / 64;
    for (int t = 0; t < NT; t++) {
        CP_WAIT(0);
        __syncthreads();
        if (t + 1 < NT)
            f_issue_kv(Kb, Vb, (t + 1) * 64, kv_base + ((t + 1) & 1) * KVSTAGE_B, tid);

        const uint32_t ksb = kv_base + (t & 1) * KVSTAGE_B;
        const uint32_t vsb = ksb + 64 * QSTR * 2;

        // ---- S' = (Q*scale*log2e) K^T ----
        float s[8][4];
        #pragma unroll
        for (int nt = 0; nt < 8; nt++)
            #pragma unroll
            for (int r = 0; r < 4; r++) s[nt][r] = 0.f;
        #pragma unroll
        for (int ks = 0; ks < 4; ks++) {
            const int co = ks * 16 + colb;
            uint32_t kf[4][4];
            #pragma unroll
            for (int p = 0; p < 4; p++)
                ldsm4(kf[p], ksb + ((p * 16 + lr8) * QSTR + co) * 2);
            #pragma unroll
            for (int nt = 0; nt < 8; nt++)
                mma_f16(s[nt], qf[ks],
                        kf[nt >> 1][nt & 1], kf[nt >> 1][(nt & 1) + 2]);
        }

        // ---- P = exp2(S') (no max pass) ----
        #pragma unroll
        for (int nt = 0; nt < 8; nt++) {
            s[nt][0] = ex2(s[nt][0]);
            s[nt][1] = ex2(s[nt][1]);
            s[nt][2] = ex2(s[nt][2]);
            s[nt][3] = ex2(s[nt][3]);
        }

        // ---- O += P V; row sums via ones-column mma ----
        #pragma unroll
        for (int ks = 0; ks < 4; ks++) {
            uint32_t af[4];
            af[0] = f2h2(s[2 * ks][0],     s[2 * ks][1]);
            af[1] = f2h2(s[2 * ks][2],     s[2 * ks][3]);
            af[2] = f2h2(s[2 * ks + 1][0], s[2 * ks + 1][1]);
            af[3] = f2h2(s[2 * ks + 1][2], s[2 * ks + 1][3]);
            const int co = ks * 16 + colb;
            uint32_t vf[4][4];
            #pragma unroll
            for (int p = 0; p < 4; p++)
                ldsm4(vf[p], vsb + ((p * 16 + lr8) * QSTR + co) * 2);
            #pragma unroll
            for (int nt = 0; nt < 8; nt++)
                mma_f16(acc_o[nt], af,
                        vf[nt >> 1][nt & 1], vf[nt >> 1][(nt & 1) + 2]);
            mma_f16(acc_s, af, bones, bones);
        }
    }

    // ---- epilogue ----
    const int src = lane & ~3;
    const float l0 = __shfl_sync(0xffffffff, acc_s[0], src);
    const float l1 = __shfl_sync(0xffffffff, acc_s[2], src);
    const float inv0 = 1.f / l0, inv1 = 1.f / l1;
    const int r0 = q0 + warp * 16 + (lane >> 2);
    const int r1 = r0 + 8;
    __half* Ob0 = Out + ((size_t)b * SEQ + r0) * DIM + h * HDIM;
    __half* Ob1 = Out + ((size_t)b * SEQ + r1) * DIM + h * HDIM;
    #pragma unroll
    for (int nt = 0; nt < 8; nt++) {
        const int c = nt * 8 + (lane & 3) * 2;
        *(__half2*)(Ob0 + c) = __floats2half2_rn(acc_o[nt][0] * inv0, acc_o[nt][1] * inv0);
        *(__half2*)(Ob1 + c) = __floats2half2_rn(acc_o[nt][2] * inv1, acc_o[nt][3] * inv1);
    }
}

// ---------------------------------------------------------------------------
// kernel_launch
// ---------------------------------------------------------------------------
extern "C" void kernel_launch(void* const* d_in, const int* in_sizes, int n_in,
                              void* d_out, int out_size)
{
    const float* X  = (const float*)d_in[0];
    const float* Wq = (const float*)d_in[1];
    const float* bq = (const float*)d_in[2];
    const float* Wk = (const float*)d_in[3];
    const float* bk = (const float*)d_in[4];
    const float* Wv = (const float*)d_in[5];
    const float* bv = (const float*)d_in[6];
    const float* Wo = (const float*)d_in[7];
    const float* bo = (const float*)d_in[8];
    float* out = (float*)d_out;

    __half *xh, *wt, *qh, *kh, *vh, *ah;
    cudaGetSymbolAddress((void**)&xh, g_Xh);
    cudaGetSymbolAddress((void**)&wt, g_WTh);
    cudaGetSymbolAddress((void**)&qh, g_Qh);
    cudaGetSymbolAddress((void**)&kh, g_Kh);
    cudaGetSymbolAddress((void**)&vh, g_Vh);
    cudaGetSymbolAddress((void**)&ah, g_attnh);

    static bool attr_set = false;
    if (!attr_set) {
        cudaFuncSetAttribute(qkv_h,
            cudaFuncAttributeMaxDynamicSharedMemorySize, GEMM_SMEM);
        cudaFuncSetAttribute(out_h,
            cudaFuncAttributeMaxDynamicSharedMemorySize, GEMM_SMEM);
        cudaFuncSetAttribute(flash_h,
            cudaFuncAttributeMaxDynamicSharedMemorySize, FLASH_SMEM);
        attr_set = true;
    }

    // 1. Prep: convert X + transpose/convert all 4 weights (single launch)
    const dim3 pGrid(32, 32, 5);
    const dim3 pBlk(32, 8);
    prep<<<pGrid, pBlk>>>(X, Wq, Wk, Wv, Wo, xh, wt);

    // 2. QKV projections (128 threads, 4 warps of 64x64)
    const dim3 qkvGrid(DIM / 128, MROWS / 128, 3);   // (8, 64, 3)
    qkv_h<<<qkvGrid, 128, GEMM_SMEM>>>(xh, wt, bq, bk, bv, qh, kh, vh);

    // 3. Fused attention
    const dim3 faGrid(SEQ / 128, HEADS, BATCH);      // (16, 16, 4)
    flash_h<<<faGrid, 256, FLASH_SMEM>>>(qh, kh, vh, ah);

    // 4. Output projection
    const dim3 projGrid(DIM / 128, MROWS / 128);     // (8, 64)
    out_h<<<projGrid, 128, GEMM_SMEM>>>(ah, wt + 3 * (size_t)DIM * DIM, bo, out);
}